// round 1
// baseline (speedup 1.0000x reference)
#include <cuda_runtime.h>
#include <cuda_bf16.h>
#include <math.h>

#define B_   64
#define Q_   64
#define T_   448
#define D_   512
#define FD_  1024
#define H_   8
#define DH_  64
#define FF_  2048
#define S_   512
#define BS_  (B_ * S_)   // 32768
#define BT_  (B_ * T_)   // 28672

// ---------------- scratch (static device globals; no allocation) ----------------
__device__ float g_x[BS_ * D_];
__device__ float g_q[BS_ * D_];
__device__ float g_k[BS_ * D_];
__device__ float g_v[BS_ * D_];
__device__ float g_ctx[BS_ * D_];
__device__ float g_y[BS_ * D_];
__device__ float g_h[(size_t)BS_ * FF_];
__device__ float g_vproj[(size_t)BT_ * D_];

// ---------------- helpers ----------------
__device__ __forceinline__ float4 ld4(const float* p) { return *(const float4*)p; }
__device__ __forceinline__ void st4(float* p, float4 v) { *(float4*)p = v; }

// block of 128 threads
__device__ __forceinline__ float block_sum(float v, float* sm) {
#pragma unroll
    for (int o = 16; o; o >>= 1) v += __shfl_xor_sync(0xffffffffu, v, o);
    int w = threadIdx.x >> 5;
    __syncthreads();
    if ((threadIdx.x & 31) == 0) sm[w] = v;
    __syncthreads();
    return (sm[0] + sm[1]) + (sm[2] + sm[3]);
}

// LayerNorm over D=512, 128 threads x 4 elems, eps inside sqrt per reference
__device__ __forceinline__ void block_ln(float4& v, int i0,
                                         const float* __restrict__ g,
                                         const float* __restrict__ b,
                                         float* sm) {
    float s = v.x + v.y + v.z + v.w;
    s = block_sum(s, sm);
    float mean = s * (1.0f / (float)D_);
    float dx = v.x - mean, dy = v.y - mean, dz = v.z - mean, dw = v.w - mean;
    float ss = dx * dx + dy * dy + dz * dz + dw * dw;
    ss = block_sum(ss, sm);
    float inv = rsqrtf(ss * (1.0f / (float)D_) + 1e-12f);
    float4 gg = ld4(g + i0), bb = ld4(b + i0);
    v.x = dx * inv * gg.x + bb.x;
    v.y = dy * inv * gg.y + bb.y;
    v.z = dz * inv * gg.z + bb.z;
    v.w = dw * inv * gg.w + bb.w;
}

// ---------------- GEMM: C = epilogue(A @ W + bias) ----------------
// A [M,K] row-major, W [K,N] row-major, C [M,N]. M%128==0, N%128==0, K%8==0.
// MODE: 0 = bias, 1 = (bias)*scale, 2 = gelu(bias)
#define BM 128
#define BN 128
#define BK 8

template<int MODE>
__global__ __launch_bounds__(256, 2)
void gemm_bias_kernel(const float* __restrict__ A, const float* __restrict__ W,
                      const float* __restrict__ bias, float* __restrict__ C,
                      int M, int Nc, int K, float scale) {
    __shared__ float As[BK][BM];
    __shared__ float Bs[BK][BN];
    int tid = threadIdx.x;
    int bx = blockIdx.x;           // N tile
    int by = blockIdx.y;           // M tile

    const float* Ab = A + (size_t)by * BM * K;
    const float* Bb = W + (size_t)bx * BN;

    int arow = tid >> 1, acol = (tid & 1) * 4;
    int brow = tid >> 5, bcol = (tid & 31) * 4;
    int tx = tid & 15, ty = tid >> 4;

    float acc[8][8];
#pragma unroll
    for (int i = 0; i < 8; ++i)
#pragma unroll
        for (int j = 0; j < 8; ++j) acc[i][j] = 0.0f;

    float4 apre = ld4(Ab + (size_t)arow * K + acol);
    float4 bpre = ld4(Bb + (size_t)brow * Nc + bcol);

    int ktiles = K / BK;
    for (int t = 0; t < ktiles; ++t) {
        As[acol + 0][arow] = apre.x;
        As[acol + 1][arow] = apre.y;
        As[acol + 2][arow] = apre.z;
        As[acol + 3][arow] = apre.w;
        *(float4*)&Bs[brow][bcol] = bpre;
        __syncthreads();
        if (t + 1 < ktiles) {
            apre = ld4(Ab + (size_t)arow * K + (size_t)(t + 1) * BK + acol);
            bpre = ld4(Bb + ((size_t)(t + 1) * BK + brow) * Nc + bcol);
        }
#pragma unroll
        for (int k = 0; k < BK; ++k) {
            float a[8], b[8];
            *(float4*)(a)     = *(float4*)&As[k][ty * 8];
            *(float4*)(a + 4) = *(float4*)&As[k][ty * 8 + 4];
            *(float4*)(b)     = *(float4*)&Bs[k][tx * 8];
            *(float4*)(b + 4) = *(float4*)&Bs[k][tx * 8 + 4];
#pragma unroll
            for (int i = 0; i < 8; ++i)
#pragma unroll
                for (int j = 0; j < 8; ++j)
                    acc[i][j] = fmaf(a[i], b[j], acc[i][j]);
        }
        __syncthreads();
    }

    int crow0 = by * BM + ty * 8;
    int ccol0 = bx * BN + tx * 8;
#pragma unroll
    for (int i = 0; i < 8; ++i) {
#pragma unroll
        for (int jj = 0; jj < 2; ++jj) {
            float4 r;
            float vals[4];
#pragma unroll
            for (int u = 0; u < 4; ++u) {
                float val = acc[i][jj * 4 + u] + bias[ccol0 + jj * 4 + u];
                if (MODE == 1) val *= scale;
                if (MODE == 2) val = 0.5f * val * (1.0f + erff(val * 0.70710678118654752f));
                vals[u] = val;
            }
            r.x = vals[0]; r.y = vals[1]; r.z = vals[2]; r.w = vals[3];
            st4(&C[(size_t)(crow0 + i) * Nc + ccol0 + jj * 4], r);
        }
    }
}

// ---------------- build x: concat(question, LN(vproj)) + pos + mod, LN ----------------
__global__ void build_x_kernel(const float* __restrict__ question,
                               const float* __restrict__ vproj,
                               const float* __restrict__ pos_emb,
                               const float* __restrict__ mod_emb,
                               const float* __restrict__ nv_g, const float* __restrict__ nv_b,
                               const float* __restrict__ emb_g, const float* __restrict__ emb_b,
                               float* __restrict__ x) {
    __shared__ float sm[4];
    int row = blockIdx.x;
    int b = row / S_, s = row % S_;
    int i0 = threadIdx.x * 4;
    float4 v;
    if (s < Q_) {
        v = ld4(question + ((size_t)b * Q_ + s) * D_ + i0);
    } else {
        v = ld4(vproj + ((size_t)b * T_ + (s - Q_)) * D_ + i0);
        block_ln(v, i0, nv_g, nv_b, sm);
    }
    float4 pe = ld4(pos_emb + (size_t)s * D_ + i0);
    const float* me_p = mod_emb + (size_t)(s < Q_ ? 0 : 1) * D_ + i0;
    float4 me = ld4(me_p);
    v.x += pe.x + me.x; v.y += pe.y + me.y; v.z += pe.z + me.z; v.w += pe.w + me.w;
    block_ln(v, i0, emb_g, emb_b, sm);
    st4(x + (size_t)row * D_ + i0, v);
}

// ---------------- residual + LN: out = LN(y + res) ----------------
__global__ void add_ln_kernel(const float* __restrict__ y, const float* __restrict__ res,
                              float* __restrict__ out,
                              const float* __restrict__ g, const float* __restrict__ bta) {
    __shared__ float sm[4];
    int row = blockIdx.x;
    int i0 = threadIdx.x * 4;
    size_t off = (size_t)row * D_ + i0;
    float4 a = ld4(y + off), r = ld4(res + off);
    float4 v = make_float4(a.x + r.x, a.y + r.y, a.z + r.z, a.w + r.w);
    block_ln(v, i0, g, bta, sm);
    st4(out + off, v);
}

// ---------------- attention: flash-style, one warp per query row ----------------
__global__ __launch_bounds__(256)
void attn_kernel(const float* __restrict__ q, const float* __restrict__ k,
                 const float* __restrict__ v, const int* __restrict__ mask,
                 float* __restrict__ ctx) {
    int bh = blockIdx.x;
    int b = bh >> 3, h = bh & 7;
    int w = threadIdx.x >> 5, lane = threadIdx.x & 31;
    int qi = blockIdx.y * 8 + w;

    size_t qoff = ((size_t)b * S_ + qi) * D_ + h * DH_;
    float q0 = q[qoff + lane], q1 = q[qoff + 32 + lane];

    const float* kb = k + (size_t)b * S_ * D_ + h * DH_;
    const float* vb = v + (size_t)b * S_ * D_ + h * DH_;
    const int* mb = mask + b * S_;

    float m = -INFINITY, l = 0.0f, a0 = 0.0f, a1 = 0.0f;
    for (int j = 0; j < S_; ++j) {
        size_t ko = (size_t)j * D_;
        float k0 = kb[ko + lane], k1 = kb[ko + 32 + lane];
        float s = q0 * k0 + q1 * k1;
#pragma unroll
        for (int o = 16; o; o >>= 1) s += __shfl_xor_sync(0xffffffffu, s, o);
        if (mb[j] == 0) s = -INFINITY;
        float nm = fmaxf(m, s);
        if (nm != -INFINITY) {
            float corr = __expf(m - nm);
            float p = __expf(s - nm);
            float v0 = vb[ko + lane], v1 = vb[ko + 32 + lane];
            l = l * corr + p;
            a0 = a0 * corr + p * v0;
            a1 = a1 * corr + p * v1;
            m = nm;
        }
    }
    float inv = 1.0f / l;
    ctx[qoff + lane] = a0 * inv;
    ctx[qoff + 32 + lane] = a1 * inv;
}

// ---------------- launcher ----------------
extern "C" void kernel_launch(void* const* d_in, const int* in_sizes, int n_in,
                              void* d_out, int out_size) {
    const float* video    = (const float*)d_in[0];
    const float* question = (const float*)d_in[1];
    const int*   mask     = (const int*)d_in[2];
    const float* pos_emb  = (const float*)d_in[3];
    const float* mod_emb  = (const float*)d_in[4];
    const float* Wv   = (const float*)d_in[5];
    const float* bv   = (const float*)d_in[6];
    const float* nv_g = (const float*)d_in[7];
    const float* nv_b = (const float*)d_in[8];
    const float* emb_g = (const float*)d_in[9];
    const float* emb_b = (const float*)d_in[10];
    const float* Wq  = (const float*)d_in[11];
    const float* bq  = (const float*)d_in[12];
    const float* Wk  = (const float*)d_in[13];
    const float* bk  = (const float*)d_in[14];
    const float* Wva = (const float*)d_in[15];
    const float* bva = (const float*)d_in[16];
    const float* Wo  = (const float*)d_in[17];
    const float* bo  = (const float*)d_in[18];
    const float* ln1_g = (const float*)d_in[19];
    const float* ln1_b = (const float*)d_in[20];
    const float* W1  = (const float*)d_in[21];
    const float* b1  = (const float*)d_in[22];
    const float* W2  = (const float*)d_in[23];
    const float* b2  = (const float*)d_in[24];
    const float* ln2_g = (const float*)d_in[25];
    const float* ln2_b = (const float*)d_in[26];
    float* out = (float*)d_out;

    float *x, *qb, *kb, *vb, *ctx, *yb, *hb, *vproj;
    cudaGetSymbolAddress((void**)&x,     g_x);
    cudaGetSymbolAddress((void**)&qb,    g_q);
    cudaGetSymbolAddress((void**)&kb,    g_k);
    cudaGetSymbolAddress((void**)&vb,    g_v);
    cudaGetSymbolAddress((void**)&ctx,   g_ctx);
    cudaGetSymbolAddress((void**)&yb,    g_y);
    cudaGetSymbolAddress((void**)&hb,    g_h);
    cudaGetSymbolAddress((void**)&vproj, g_vproj);

    // 1) video projection: vproj = video @ Wv + bv   [BT, D]
    gemm_bias_kernel<0><<<dim3(D_ / BN, BT_ / BM), 256>>>(video, Wv, bv, vproj, BT_, D_, FD_, 1.0f);

    // 2) x = LN(concat(question, LN(vproj)) + pos + mod)
    build_x_kernel<<<BS_, 128>>>(question, vproj, pos_emb, mod_emb, nv_g, nv_b, emb_g, emb_b, x);

    const float scale = 0.125f;  // 1/sqrt(64)
    for (int i = 0; i < 2; ++i) {
        const float* Wqi = Wq + (size_t)i * D_ * D_;
        const float* Wki = Wk + (size_t)i * D_ * D_;
        const float* Wvi = Wva + (size_t)i * D_ * D_;
        const float* Woi = Wo + (size_t)i * D_ * D_;
        const float* W1i = W1 + (size_t)i * D_ * FF_;
        const float* W2i = W2 + (size_t)i * FF_ * D_;

        gemm_bias_kernel<1><<<dim3(D_ / BN, BS_ / BM), 256>>>(x, Wqi, bq + i * D_, qb, BS_, D_, D_, scale);
        gemm_bias_kernel<0><<<dim3(D_ / BN, BS_ / BM), 256>>>(x, Wki, bk + i * D_, kb, BS_, D_, D_, 1.0f);
        gemm_bias_kernel<0><<<dim3(D_ / BN, BS_ / BM), 256>>>(x, Wvi, bva + i * D_, vb, BS_, D_, D_, 1.0f);

        attn_kernel<<<dim3(B_ * H_, S_ / 8), 256>>>(qb, kb, vb, mask, ctx);

        gemm_bias_kernel<0><<<dim3(D_ / BN, BS_ / BM), 256>>>(ctx, Woi, bo + i * D_, yb, BS_, D_, D_, 1.0f);
        add_ln_kernel<<<BS_, 128>>>(yb, x, x, ln1_g + i * D_, ln1_b + i * D_);

        gemm_bias_kernel<2><<<dim3(FF_ / BN, BS_ / BM), 256>>>(x, W1i, b1 + i * FF_, hb, BS_, FF_, D_, 1.0f);
        gemm_bias_kernel<0><<<dim3(D_ / BN, BS_ / BM), 256>>>(hb, W2i, b2 + i * D_, yb, BS_, D_, FF_, 1.0f);

        float* dst = (i == 1) ? out : x;
        add_ln_kernel<<<BS_, 128>>>(yb, x, dst, ln2_g + i * D_, ln2_b + i * D_);
    }
    (void)in_sizes; (void)n_in; (void)out_size;
}

// round 2
// speedup vs baseline: 1.2260x; 1.2260x over previous
#include <cuda_runtime.h>
#include <cuda_bf16.h>
#include <math.h>

#define B_   64
#define Q_   64
#define T_   448
#define D_   512
#define FD_  1024
#define H_   8
#define DH_  64
#define FF_  2048
#define S_   512
#define BS_  (B_ * S_)   // 32768
#define BT_  (B_ * T_)   // 28672

// ---------------- scratch (static device globals; no allocation) ----------------
__device__ float g_x[BS_ * D_];
__device__ float g_q[BS_ * D_];
__device__ float g_k[BS_ * D_];
__device__ float g_v[BS_ * D_];
__device__ float g_ctx[BS_ * D_];
__device__ float g_y[BS_ * D_];
__device__ float g_h[(size_t)BS_ * FF_];
__device__ float g_vproj[(size_t)BT_ * D_];

// split/transposed weights: hi + lo bf16, layout [N][K]
#define WSPLIT_TOTAL 6815744
__device__ __nv_bfloat16 g_wh[WSPLIT_TOTAL];
__device__ __nv_bfloat16 g_wl[WSPLIT_TOTAL];

// ---------------- helpers ----------------
__device__ __forceinline__ float4 ld4(const float* p) { return *(const float4*)p; }
__device__ __forceinline__ void st4(float* p, float4 v) { *(float4*)p = v; }

__device__ __forceinline__ float block_sum(float v, float* sm) {
#pragma unroll
    for (int o = 16; o; o >>= 1) v += __shfl_xor_sync(0xffffffffu, v, o);
    int w = threadIdx.x >> 5;
    __syncthreads();
    if ((threadIdx.x & 31) == 0) sm[w] = v;
    __syncthreads();
    return (sm[0] + sm[1]) + (sm[2] + sm[3]);
}

__device__ __forceinline__ void block_ln(float4& v, int i0,
                                         const float* __restrict__ g,
                                         const float* __restrict__ b,
                                         float* sm) {
    float s = v.x + v.y + v.z + v.w;
    s = block_sum(s, sm);
    float mean = s * (1.0f / (float)D_);
    float dx = v.x - mean, dy = v.y - mean, dz = v.z - mean, dw = v.w - mean;
    float ss = dx * dx + dy * dy + dz * dz + dw * dw;
    ss = block_sum(ss, sm);
    float inv = rsqrtf(ss * (1.0f / (float)D_) + 1e-12f);
    float4 gg = ld4(g + i0), bb = ld4(b + i0);
    v.x = dx * inv * gg.x + bb.x;
    v.y = dy * inv * gg.y + bb.y;
    v.z = dz * inv * gg.z + bb.z;
    v.w = dw * inv * gg.w + bb.w;
}

// ---------------- weight transpose+split: T[n][k] = W[k][n] as bf16 hi/lo ----------------
__global__ void split_w_kernel(const float* __restrict__ W, int K, int N,
                               __nv_bfloat16* __restrict__ Th, __nv_bfloat16* __restrict__ Tl) {
    __shared__ float tile[32][33];
    int k0 = blockIdx.y * 32, n0 = blockIdx.x * 32;
    int tx = threadIdx.x, ty = threadIdx.y;
    for (int j = ty; j < 32; j += 8)
        tile[j][tx] = W[(size_t)(k0 + j) * N + n0 + tx];
    __syncthreads();
    for (int j = ty; j < 32; j += 8) {
        float v = tile[tx][j];                  // W[k0+tx][n0+j]
        __nv_bfloat16 hi = __float2bfloat16(v);
        __nv_bfloat16 lo = __float2bfloat16(v - __bfloat162float(hi));
        size_t o = (size_t)(n0 + j) * K + k0 + tx;
        Th[o] = hi; Tl[o] = lo;
    }
}

// ---------------- tensor-core GEMM (bf16x3 compensated) ----------------
// C = epilogue(A @ W + bias); A [M,K] fp32 row-major; W presplit [N][K] bf16 hi/lo
// MODE: 0 = bias, 1 = bias*scale, 2 = gelu(bias)
#define TBM 128
#define TBN 128
#define TBK 32
#define LDA 40   // TBK + 8 pad (bf16 elems) -> 80B row stride, conflict-free ldsm

__device__ __forceinline__ void mma16816(float* d, const unsigned* a, const unsigned* b) {
    asm volatile(
        "mma.sync.aligned.m16n8k16.row.col.f32.bf16.bf16.f32 "
        "{%0,%1,%2,%3}, {%4,%5,%6,%7}, {%8,%9}, {%0,%1,%2,%3};\n"
        : "+f"(d[0]), "+f"(d[1]), "+f"(d[2]), "+f"(d[3])
        : "r"(a[0]), "r"(a[1]), "r"(a[2]), "r"(a[3]), "r"(b[0]), "r"(b[1]));
}
__device__ __forceinline__ void ldsm4(unsigned* r, unsigned addr) {
    asm volatile("ldmatrix.sync.aligned.m8n8.x4.shared.b16 {%0,%1,%2,%3}, [%4];\n"
                 : "=r"(r[0]), "=r"(r[1]), "=r"(r[2]), "=r"(r[3]) : "r"(addr));
}
__device__ __forceinline__ void ldsm2(unsigned* r, unsigned addr) {
    asm volatile("ldmatrix.sync.aligned.m8n8.x2.shared.b16 {%0,%1}, [%2];\n"
                 : "=r"(r[0]), "=r"(r[1]) : "r"(addr));
}

template<int MODE>
__global__ __launch_bounds__(256, 2)
void gemm_tc_kernel(const float* __restrict__ A,
                    const __nv_bfloat16* __restrict__ Wh,
                    const __nv_bfloat16* __restrict__ Wl,
                    const float* __restrict__ bias, float* __restrict__ C,
                    int M, int N, int K, float scale) {
    __shared__ __nv_bfloat16 Ah[TBM][LDA], Al[TBM][LDA];
    __shared__ __nv_bfloat16 Bh[TBN][LDA], Bl[TBN][LDA];

    int tid = threadIdx.x;
    int lane = tid & 31, wid = tid >> 5;
    int warpM = wid & 1, warpN = wid >> 1;   // 2 x 4 warps
    int m0 = warpM * 64, n0 = warpN * 32;

    int blockM = blockIdx.y * TBM;
    int blockN = blockIdx.x * TBN;

    // lane-dependent ldsm row/col selects
    int a_row = lane & 15, a_cs = (lane >> 4) * 8;
    int b_row = lane & 7,  b_cs = ((lane >> 3) & 1) * 8;

    float acc[4][4][4];
#pragma unroll
    for (int f = 0; f < 4; ++f)
#pragma unroll
        for (int g = 0; g < 4; ++g)
#pragma unroll
            for (int j = 0; j < 4; ++j) acc[f][g][j] = 0.0f;

    int ktiles = K / TBK;
    for (int kt = 0; kt < ktiles; ++kt) {
        // ---- stage A (fp32 -> bf16 hi/lo) ----
        {
            int r = tid >> 3;            // 0..31
            int c4 = (tid & 7) * 4;      // 0..28
            const float* Ab = A + (size_t)(blockM + r) * K + kt * TBK + c4;
#pragma unroll
            for (int wv = 0; wv < 4; ++wv) {
                float4 a4 = ld4(Ab + (size_t)wv * 32 * K);
                int rr = r + wv * 32;
                __nv_bfloat16 h0 = __float2bfloat16(a4.x);
                __nv_bfloat16 h1 = __float2bfloat16(a4.y);
                __nv_bfloat16 h2 = __float2bfloat16(a4.z);
                __nv_bfloat16 h3 = __float2bfloat16(a4.w);
                __nv_bfloat16 l0 = __float2bfloat16(a4.x - __bfloat162float(h0));
                __nv_bfloat16 l1 = __float2bfloat16(a4.y - __bfloat162float(h1));
                __nv_bfloat16 l2 = __float2bfloat16(a4.z - __bfloat162float(h2));
                __nv_bfloat16 l3 = __float2bfloat16(a4.w - __bfloat162float(h3));
                *(__nv_bfloat162*)&Ah[rr][c4]     = __nv_bfloat162(h0, h1);
                *(__nv_bfloat162*)&Ah[rr][c4 + 2] = __nv_bfloat162(h2, h3);
                *(__nv_bfloat162*)&Al[rr][c4]     = __nv_bfloat162(l0, l1);
                *(__nv_bfloat162*)&Al[rr][c4 + 2] = __nv_bfloat162(l2, l3);
            }
        }
        // ---- stage B (bf16 copies) ----
        {
#pragma unroll
            for (int wv = 0; wv < 2; ++wv) {
                int idx = tid + wv * 256;     // 0..511
                int r = idx >> 2;             // 0..127
                int c8 = (idx & 3) * 8;       // 0..24
                size_t go = (size_t)(blockN + r) * K + kt * TBK + c8;
                *(uint4*)&Bh[r][c8] = *(const uint4*)(Wh + go);
                *(uint4*)&Bl[r][c8] = *(const uint4*)(Wl + go);
            }
        }
        __syncthreads();

        // ---- compute: 2 k16 chunks x 3 compensated terms ----
#pragma unroll
        for (int kc = 0; kc < TBK; kc += 16) {
            unsigned aF[16], bHf[8], bLf[8];
#pragma unroll
            for (int f = 0; f < 4; ++f)
                ldsm4(aF + 4 * f, (unsigned)__cvta_generic_to_shared(
                    &Ah[m0 + f * 16 + a_row][kc + a_cs]));
#pragma unroll
            for (int g = 0; g < 4; ++g)
                ldsm2(bHf + 2 * g, (unsigned)__cvta_generic_to_shared(
                    &Bh[n0 + g * 8 + b_row][kc + b_cs]));
#pragma unroll
            for (int g = 0; g < 4; ++g)
                ldsm2(bLf + 2 * g, (unsigned)__cvta_generic_to_shared(
                    &Bl[n0 + g * 8 + b_row][kc + b_cs]));
            // hi * hi
#pragma unroll
            for (int f = 0; f < 4; ++f)
#pragma unroll
                for (int g = 0; g < 4; ++g)
                    mma16816(acc[f][g], aF + 4 * f, bHf + 2 * g);
            // hi * lo
#pragma unroll
            for (int f = 0; f < 4; ++f)
#pragma unroll
                for (int g = 0; g < 4; ++g)
                    mma16816(acc[f][g], aF + 4 * f, bLf + 2 * g);
            // lo * hi
#pragma unroll
            for (int f = 0; f < 4; ++f)
                ldsm4(aF + 4 * f, (unsigned)__cvta_generic_to_shared(
                    &Al[m0 + f * 16 + a_row][kc + a_cs]));
#pragma unroll
            for (int f = 0; f < 4; ++f)
#pragma unroll
                for (int g = 0; g < 4; ++g)
                    mma16816(acc[f][g], aF + 4 * f, bHf + 2 * g);
        }
        __syncthreads();
    }

    // ---- epilogue ----
#pragma unroll
    for (int f = 0; f < 4; ++f) {
#pragma unroll
        for (int g = 0; g < 4; ++g) {
            int col = blockN + n0 + g * 8 + (lane & 3) * 2;
            float b0 = bias[col], b1 = bias[col + 1];
#pragma unroll
            for (int half = 0; half < 2; ++half) {
                int row = blockM + m0 + f * 16 + (lane >> 2) + half * 8;
                float v0 = acc[f][g][half * 2 + 0] + b0;
                float v1 = acc[f][g][half * 2 + 1] + b1;
                if (MODE == 1) { v0 *= scale; v1 *= scale; }
                if (MODE == 2) {
                    v0 = 0.5f * v0 * (1.0f + erff(v0 * 0.70710678118654752f));
                    v1 = 0.5f * v1 * (1.0f + erff(v1 * 0.70710678118654752f));
                }
                *(float2*)&C[(size_t)row * N + col] = make_float2(v0, v1);
            }
        }
    }
}

// ---------------- build x ----------------
__global__ void build_x_kernel(const float* __restrict__ question,
                               const float* __restrict__ vproj,
                               const float* __restrict__ pos_emb,
                               const float* __restrict__ mod_emb,
                               const float* __restrict__ nv_g, const float* __restrict__ nv_b,
                               const float* __restrict__ emb_g, const float* __restrict__ emb_b,
                               float* __restrict__ x) {
    __shared__ float sm[4];
    int row = blockIdx.x;
    int b = row / S_, s = row % S_;
    int i0 = threadIdx.x * 4;
    float4 v;
    if (s < Q_) {
        v = ld4(question + ((size_t)b * Q_ + s) * D_ + i0);
    } else {
        v = ld4(vproj + ((size_t)b * T_ + (s - Q_)) * D_ + i0);
        block_ln(v, i0, nv_g, nv_b, sm);
    }
    float4 pe = ld4(pos_emb + (size_t)s * D_ + i0);
    const float* me_p = mod_emb + (size_t)(s < Q_ ? 0 : 1) * D_ + i0;
    float4 me = ld4(me_p);
    v.x += pe.x + me.x; v.y += pe.y + me.y; v.z += pe.z + me.z; v.w += pe.w + me.w;
    block_ln(v, i0, emb_g, emb_b, sm);
    st4(x + (size_t)row * D_ + i0, v);
}

// ---------------- residual + LN ----------------
__global__ void add_ln_kernel(const float* __restrict__ y, const float* __restrict__ res,
                              float* __restrict__ out,
                              const float* __restrict__ g, const float* __restrict__ bta) {
    __shared__ float sm[4];
    int row = blockIdx.x;
    int i0 = threadIdx.x * 4;
    size_t off = (size_t)row * D_ + i0;
    float4 a = ld4(y + off), r = ld4(res + off);
    float4 v = make_float4(a.x + r.x, a.y + r.y, a.z + r.z, a.w + r.w);
    block_ln(v, i0, g, bta, sm);
    st4(out + off, v);
}

// ---------------- attention (flash-style, one warp per query row) ----------------
__global__ __launch_bounds__(256)
void attn_kernel(const float* __restrict__ q, const float* __restrict__ k,
                 const float* __restrict__ v, const int* __restrict__ mask,
                 float* __restrict__ ctx) {
    int bh = blockIdx.x;
    int b = bh >> 3, h = bh & 7;
    int w = threadIdx.x >> 5, lane = threadIdx.x & 31;
    int qi = blockIdx.y * 8 + w;

    size_t qoff = ((size_t)b * S_ + qi) * D_ + h * DH_;
    float q0 = q[qoff + lane], q1 = q[qoff + 32 + lane];

    const float* kb = k + (size_t)b * S_ * D_ + h * DH_;
    const float* vb = v + (size_t)b * S_ * D_ + h * DH_;
    const int* mb = mask + b * S_;

    float m = -INFINITY, l = 0.0f, a0 = 0.0f, a1 = 0.0f;
    for (int j = 0; j < S_; ++j) {
        size_t ko = (size_t)j * D_;
        float k0 = kb[ko + lane], k1 = kb[ko + 32 + lane];
        float s = q0 * k0 + q1 * k1;
#pragma unroll
        for (int o = 16; o; o >>= 1) s += __shfl_xor_sync(0xffffffffu, s, o);
        if (mb[j] == 0) s = -INFINITY;
        float nm = fmaxf(m, s);
        if (nm != -INFINITY) {
            float corr = __expf(m - nm);
            float p = __expf(s - nm);
            float v0 = vb[ko + lane], v1 = vb[ko + 32 + lane];
            l = l * corr + p;
            a0 = a0 * corr + p * v0;
            a1 = a1 * corr + p * v1;
            m = nm;
        }
    }
    float inv = 1.0f / l;
    ctx[qoff + lane] = a0 * inv;
    ctx[qoff + 32 + lane] = a1 * inv;
}

// ---------------- launcher ----------------
extern "C" void kernel_launch(void* const* d_in, const int* in_sizes, int n_in,
                              void* d_out, int out_size) {
    const float* video    = (const float*)d_in[0];
    const float* question = (const float*)d_in[1];
    const int*   mask     = (const int*)d_in[2];
    const float* pos_emb  = (const float*)d_in[3];
    const float* mod_emb  = (const float*)d_in[4];
    const float* Wv   = (const float*)d_in[5];
    const float* bv   = (const float*)d_in[6];
    const float* nv_g = (const float*)d_in[7];
    const float* nv_b = (const float*)d_in[8];
    const float* emb_g = (const float*)d_in[9];
    const float* emb_b = (const float*)d_in[10];
    const float* Wq  = (const float*)d_in[11];
    const float* bq  = (const float*)d_in[12];
    const float* Wk  = (const float*)d_in[13];
    const float* bk  = (const float*)d_in[14];
    const float* Wva = (const float*)d_in[15];
    const float* bva = (const float*)d_in[16];
    const float* Wo  = (const float*)d_in[17];
    const float* bo  = (const float*)d_in[18];
    const float* ln1_g = (const float*)d_in[19];
    const float* ln1_b = (const float*)d_in[20];
    const float* W1  = (const float*)d_in[21];
    const float* b1  = (const float*)d_in[22];
    const float* W2  = (const float*)d_in[23];
    const float* b2  = (const float*)d_in[24];
    const float* ln2_g = (const float*)d_in[25];
    const float* ln2_b = (const float*)d_in[26];
    float* out = (float*)d_out;

    float *x, *qb, *kb, *vb, *ctx, *yb, *hb, *vproj;
    __nv_bfloat16 *wh, *wl;
    cudaGetSymbolAddress((void**)&x,     g_x);
    cudaGetSymbolAddress((void**)&qb,    g_q);
    cudaGetSymbolAddress((void**)&kb,    g_k);
    cudaGetSymbolAddress((void**)&vb,    g_v);
    cudaGetSymbolAddress((void**)&ctx,   g_ctx);
    cudaGetSymbolAddress((void**)&yb,    g_y);
    cudaGetSymbolAddress((void**)&hb,    g_h);
    cudaGetSymbolAddress((void**)&vproj, g_vproj);
    cudaGetSymbolAddress((void**)&wh,    g_wh);
    cudaGetSymbolAddress((void**)&wl,    g_wl);

    // weight split offsets (layout [N][K])
    const size_t o_wv = 0;                                    // [512][1024]
    const size_t LSTRIDE = 4 * (size_t)D_ * D_ + 2 * (size_t)D_ * FF_;
    const size_t o_l0 = o_wv + (size_t)D_ * FD_;
    auto o_wq = [&](int i) { return o_l0 + i * LSTRIDE + 0 * (size_t)D_ * D_; };
    auto o_wk = [&](int i) { return o_l0 + i * LSTRIDE + 1 * (size_t)D_ * D_; };
    auto o_wa = [&](int i) { return o_l0 + i * LSTRIDE + 2 * (size_t)D_ * D_; };
    auto o_wo = [&](int i) { return o_l0 + i * LSTRIDE + 3 * (size_t)D_ * D_; };
    auto o_w1 = [&](int i) { return o_l0 + i * LSTRIDE + 4 * (size_t)D_ * D_; };
    auto o_w2 = [&](int i) { return o_l0 + i * LSTRIDE + 4 * (size_t)D_ * D_ + (size_t)FF_ * D_; };

    // split + transpose all weights
    split_w_kernel<<<dim3(D_ / 32, FD_ / 32), dim3(32, 8)>>>(Wv, FD_, D_, wh + o_wv, wl + o_wv);
    for (int i = 0; i < 2; ++i) {
        split_w_kernel<<<dim3(D_ / 32, D_ / 32), dim3(32, 8)>>>(Wq + (size_t)i * D_ * D_, D_, D_, wh + o_wq(i), wl + o_wq(i));
        split_w_kernel<<<dim3(D_ / 32, D_ / 32), dim3(32, 8)>>>(Wk + (size_t)i * D_ * D_, D_, D_, wh + o_wk(i), wl + o_wk(i));
        split_w_kernel<<<dim3(D_ / 32, D_ / 32), dim3(32, 8)>>>(Wva + (size_t)i * D_ * D_, D_, D_, wh + o_wa(i), wl + o_wa(i));
        split_w_kernel<<<dim3(D_ / 32, D_ / 32), dim3(32, 8)>>>(Wo + (size_t)i * D_ * D_, D_, D_, wh + o_wo(i), wl + o_wo(i));
        split_w_kernel<<<dim3(FF_ / 32, D_ / 32), dim3(32, 8)>>>(W1 + (size_t)i * D_ * FF_, D_, FF_, wh + o_w1(i), wl + o_w1(i));
        split_w_kernel<<<dim3(D_ / 32, FF_ / 32), dim3(32, 8)>>>(W2 + (size_t)i * FF_ * D_, FF_, D_, wh + o_w2(i), wl + o_w2(i));
    }

    // 1) video projection
    gemm_tc_kernel<0><<<dim3(D_ / TBN, BT_ / TBM), 256>>>(video, wh + o_wv, wl + o_wv, bv, vproj, BT_, D_, FD_, 1.0f);

    // 2) build x
    build_x_kernel<<<BS_, 128>>>(question, vproj, pos_emb, mod_emb, nv_g, nv_b, emb_g, emb_b, x);

    const float scale = 0.125f;  // 1/sqrt(64)
    for (int i = 0; i < 2; ++i) {
        gemm_tc_kernel<1><<<dim3(D_ / TBN, BS_ / TBM), 256>>>(x, wh + o_wq(i), wl + o_wq(i), bq + i * D_, qb, BS_, D_, D_, scale);
        gemm_tc_kernel<0><<<dim3(D_ / TBN, BS_ / TBM), 256>>>(x, wh + o_wk(i), wl + o_wk(i), bk + i * D_, kb, BS_, D_, D_, 1.0f);
        gemm_tc_kernel<0><<<dim3(D_ / TBN, BS_ / TBM), 256>>>(x, wh + o_wa(i), wl + o_wa(i), bva + i * D_, vb, BS_, D_, D_, 1.0f);

        attn_kernel<<<dim3(B_ * H_, S_ / 8), 256>>>(qb, kb, vb, mask, ctx);

        gemm_tc_kernel<0><<<dim3(D_ / TBN, BS_ / TBM), 256>>>(ctx, wh + o_wo(i), wl + o_wo(i), bo + i * D_, yb, BS_, D_, D_, 1.0f);
        add_ln_kernel<<<BS_, 128>>>(yb, x, x, ln1_g + i * D_, ln1_b + i * D_);

        gemm_tc_kernel<2><<<dim3(FF_ / TBN, BS_ / TBM), 256>>>(x, wh + o_w1(i), wl + o_w1(i), b1 + i * FF_, hb, BS_, FF_, D_, 1.0f);
        gemm_tc_kernel<0><<<dim3(D_ / TBN, BS_ / TBM), 256>>>(hb, wh + o_w2(i), wl + o_w2(i), b2 + i * D_, yb, BS_, D_, FF_, 1.0f);

        float* dst = (i == 1) ? out : x;
        add_ln_kernel<<<BS_, 128>>>(yb, x, dst, ln2_g + i * D_, ln2_b + i * D_);
    }
    (void)in_sizes; (void)n_in; (void)out_size;
}

// round 3
// speedup vs baseline: 3.1436x; 2.5642x over previous
#include <cuda_runtime.h>
#include <cuda_bf16.h>
#include <math.h>

#define B_   64
#define Q_   64
#define T_   448
#define D_   512
#define FD_  1024
#define H_   8
#define DH_  64
#define FF_  2048
#define S_   512
#define BS_  (B_ * S_)   // 32768
#define BT_  (B_ * T_)   // 28672

// ---------------- scratch (static device globals; no allocation) ----------------
__device__ float g_x[BS_ * D_];
__device__ float g_q[BS_ * D_];
__device__ float g_k[BS_ * D_];
__device__ float g_v[BS_ * D_];
__device__ float g_ctx[BS_ * D_];
__device__ float g_y[BS_ * D_];
__device__ float g_h[(size_t)BS_ * FF_];
__device__ float g_vproj[(size_t)BT_ * D_];

// split/transposed weights: hi + lo bf16, layout [N][K]
#define WSPLIT_TOTAL 6815744
__device__ __nv_bfloat16 g_wh[WSPLIT_TOTAL];
__device__ __nv_bfloat16 g_wl[WSPLIT_TOTAL];

// ---------------- helpers ----------------
__device__ __forceinline__ float4 ld4(const float* p) { return *(const float4*)p; }
__device__ __forceinline__ void st4(float* p, float4 v) { *(float4*)p = v; }

__device__ __forceinline__ float block_sum(float v, float* sm) {
#pragma unroll
    for (int o = 16; o; o >>= 1) v += __shfl_xor_sync(0xffffffffu, v, o);
    int w = threadIdx.x >> 5;
    __syncthreads();
    if ((threadIdx.x & 31) == 0) sm[w] = v;
    __syncthreads();
    return (sm[0] + sm[1]) + (sm[2] + sm[3]);
}

__device__ __forceinline__ void block_ln(float4& v, int i0,
                                         const float* __restrict__ g,
                                         const float* __restrict__ b,
                                         float* sm) {
    float s = v.x + v.y + v.z + v.w;
    s = block_sum(s, sm);
    float mean = s * (1.0f / (float)D_);
    float dx = v.x - mean, dy = v.y - mean, dz = v.z - mean, dw = v.w - mean;
    float ss = dx * dx + dy * dy + dz * dz + dw * dw;
    ss = block_sum(ss, sm);
    float inv = rsqrtf(ss * (1.0f / (float)D_) + 1e-12f);
    float4 gg = ld4(g + i0), bb = ld4(b + i0);
    v.x = dx * inv * gg.x + bb.x;
    v.y = dy * inv * gg.y + bb.y;
    v.z = dz * inv * gg.z + bb.z;
    v.w = dw * inv * gg.w + bb.w;
}

// ---------------- weight transpose+split ----------------
__global__ void split_w_kernel(const float* __restrict__ W, int K, int N,
                               __nv_bfloat16* __restrict__ Th, __nv_bfloat16* __restrict__ Tl) {
    __shared__ float tile[32][33];
    int k0 = blockIdx.y * 32, n0 = blockIdx.x * 32;
    int tx = threadIdx.x, ty = threadIdx.y;
    for (int j = ty; j < 32; j += 8)
        tile[j][tx] = W[(size_t)(k0 + j) * N + n0 + tx];
    __syncthreads();
    for (int j = ty; j < 32; j += 8) {
        float v = tile[tx][j];
        __nv_bfloat16 hi = __float2bfloat16(v);
        __nv_bfloat16 lo = __float2bfloat16(v - __bfloat162float(hi));
        size_t o = (size_t)(n0 + j) * K + k0 + tx;
        Th[o] = hi; Tl[o] = lo;
    }
}

// ---------------- tensor-core GEMM (bf16x3 compensated) ----------------
#define TBM 128
#define TBN 128
#define TBK 32
#define LDA 40

__device__ __forceinline__ void mma16816(float* d, const unsigned* a, const unsigned* b) {
    asm volatile(
        "mma.sync.aligned.m16n8k16.row.col.f32.bf16.bf16.f32 "
        "{%0,%1,%2,%3}, {%4,%5,%6,%7}, {%8,%9}, {%0,%1,%2,%3};\n"
        : "+f"(d[0]), "+f"(d[1]), "+f"(d[2]), "+f"(d[3])
        : "r"(a[0]), "r"(a[1]), "r"(a[2]), "r"(a[3]), "r"(b[0]), "r"(b[1]));
}
__device__ __forceinline__ void ldsm4(unsigned* r, unsigned addr) {
    asm volatile("ldmatrix.sync.aligned.m8n8.x4.shared.b16 {%0,%1,%2,%3}, [%4];\n"
                 : "=r"(r[0]), "=r"(r[1]), "=r"(r[2]), "=r"(r[3]) : "r"(addr));
}
__device__ __forceinline__ void ldsm2(unsigned* r, unsigned addr) {
    asm volatile("ldmatrix.sync.aligned.m8n8.x2.shared.b16 {%0,%1}, [%2];\n"
                 : "=r"(r[0]), "=r"(r[1]) : "r"(addr));
}

template<int MODE>
__global__ __launch_bounds__(256, 2)
void gemm_tc_kernel(const float* __restrict__ A,
                    const __nv_bfloat16* __restrict__ Wh,
                    const __nv_bfloat16* __restrict__ Wl,
                    const float* __restrict__ bias, float* __restrict__ C,
                    int M, int N, int K, float scale) {
    __shared__ __nv_bfloat16 Ah[TBM][LDA], Al[TBM][LDA];
    __shared__ __nv_bfloat16 Bh[TBN][LDA], Bl[TBN][LDA];

    int tid = threadIdx.x;
    int lane = tid & 31, wid = tid >> 5;
    int warpM = wid & 1, warpN = wid >> 1;
    int m0 = warpM * 64, n0 = warpN * 32;

    int blockM = blockIdx.y * TBM;
    int blockN = blockIdx.x * TBN;

    int a_row = lane & 15, a_cs = (lane >> 4) * 8;
    int b_row = lane & 7,  b_cs = ((lane >> 3) & 1) * 8;

    float acc[4][4][4];
#pragma unroll
    for (int f = 0; f < 4; ++f)
#pragma unroll
        for (int g = 0; g < 4; ++g)
#pragma unroll
            for (int j = 0; j < 4; ++j) acc[f][g][j] = 0.0f;

    int ktiles = K / TBK;
    for (int kt = 0; kt < ktiles; ++kt) {
        {
            int r = tid >> 3;
            int c4 = (tid & 7) * 4;
            const float* Ab = A + (size_t)(blockM + r) * K + kt * TBK + c4;
#pragma unroll
            for (int wv = 0; wv < 4; ++wv) {
                float4 a4 = ld4(Ab + (size_t)wv * 32 * K);
                int rr = r + wv * 32;
                __nv_bfloat16 h0 = __float2bfloat16(a4.x);
                __nv_bfloat16 h1 = __float2bfloat16(a4.y);
                __nv_bfloat16 h2 = __float2bfloat16(a4.z);
                __nv_bfloat16 h3 = __float2bfloat16(a4.w);
                __nv_bfloat16 l0 = __float2bfloat16(a4.x - __bfloat162float(h0));
                __nv_bfloat16 l1 = __float2bfloat16(a4.y - __bfloat162float(h1));
                __nv_bfloat16 l2 = __float2bfloat16(a4.z - __bfloat162float(h2));
                __nv_bfloat16 l3 = __float2bfloat16(a4.w - __bfloat162float(h3));
                *(__nv_bfloat162*)&Ah[rr][c4]     = __nv_bfloat162(h0, h1);
                *(__nv_bfloat162*)&Ah[rr][c4 + 2] = __nv_bfloat162(h2, h3);
                *(__nv_bfloat162*)&Al[rr][c4]     = __nv_bfloat162(l0, l1);
                *(__nv_bfloat162*)&Al[rr][c4 + 2] = __nv_bfloat162(l2, l3);
            }
        }
        {
#pragma unroll
            for (int wv = 0; wv < 2; ++wv) {
                int idx = tid + wv * 256;
                int r = idx >> 2;
                int c8 = (idx & 3) * 8;
                size_t go = (size_t)(blockN + r) * K + kt * TBK + c8;
                *(uint4*)&Bh[r][c8] = *(const uint4*)(Wh + go);
                *(uint4*)&Bl[r][c8] = *(const uint4*)(Wl + go);
            }
        }
        __syncthreads();

#pragma unroll
        for (int kc = 0; kc < TBK; kc += 16) {
            unsigned aF[16], bHf[8], bLf[8];
#pragma unroll
            for (int f = 0; f < 4; ++f)
                ldsm4(aF + 4 * f, (unsigned)__cvta_generic_to_shared(
                    &Ah[m0 + f * 16 + a_row][kc + a_cs]));
#pragma unroll
            for (int g = 0; g < 4; ++g)
                ldsm2(bHf + 2 * g, (unsigned)__cvta_generic_to_shared(
                    &Bh[n0 + g * 8 + b_row][kc + b_cs]));
#pragma unroll
            for (int g = 0; g < 4; ++g)
                ldsm2(bLf + 2 * g, (unsigned)__cvta_generic_to_shared(
                    &Bl[n0 + g * 8 + b_row][kc + b_cs]));
#pragma unroll
            for (int f = 0; f < 4; ++f)
#pragma unroll
                for (int g = 0; g < 4; ++g)
                    mma16816(acc[f][g], aF + 4 * f, bHf + 2 * g);
#pragma unroll
            for (int f = 0; f < 4; ++f)
#pragma unroll
                for (int g = 0; g < 4; ++g)
                    mma16816(acc[f][g], aF + 4 * f, bLf + 2 * g);
#pragma unroll
            for (int f = 0; f < 4; ++f)
                ldsm4(aF + 4 * f, (unsigned)__cvta_generic_to_shared(
                    &Al[m0 + f * 16 + a_row][kc + a_cs]));
#pragma unroll
            for (int f = 0; f < 4; ++f)
#pragma unroll
                for (int g = 0; g < 4; ++g)
                    mma16816(acc[f][g], aF + 4 * f, bHf + 2 * g);
        }
        __syncthreads();
    }

#pragma unroll
    for (int f = 0; f < 4; ++f) {
#pragma unroll
        for (int g = 0; g < 4; ++g) {
            int col = blockN + n0 + g * 8 + (lane & 3) * 2;
            float b0 = bias[col], b1 = bias[col + 1];
#pragma unroll
            for (int half = 0; half < 2; ++half) {
                int row = blockM + m0 + f * 16 + (lane >> 2) + half * 8;
                float v0 = acc[f][g][half * 2 + 0] + b0;
                float v1 = acc[f][g][half * 2 + 1] + b1;
                if (MODE == 1) { v0 *= scale; v1 *= scale; }
                if (MODE == 2) {
                    v0 = 0.5f * v0 * (1.0f + erff(v0 * 0.70710678118654752f));
                    v1 = 0.5f * v1 * (1.0f + erff(v1 * 0.70710678118654752f));
                }
                *(float2*)&C[(size_t)row * N + col] = make_float2(v0, v1);
            }
        }
    }
}

// ---------------- build x ----------------
__global__ void build_x_kernel(const float* __restrict__ question,
                               const float* __restrict__ vproj,
                               const float* __restrict__ pos_emb,
                               const float* __restrict__ mod_emb,
                               const float* __restrict__ nv_g, const float* __restrict__ nv_b,
                               const float* __restrict__ emb_g, const float* __restrict__ emb_b,
                               float* __restrict__ x) {
    __shared__ float sm[4];
    int row = blockIdx.x;
    int b = row / S_, s = row % S_;
    int i0 = threadIdx.x * 4;
    float4 v;
    if (s < Q_) {
        v = ld4(question + ((size_t)b * Q_ + s) * D_ + i0);
    } else {
        v = ld4(vproj + ((size_t)b * T_ + (s - Q_)) * D_ + i0);
        block_ln(v, i0, nv_g, nv_b, sm);
    }
    float4 pe = ld4(pos_emb + (size_t)s * D_ + i0);
    const float* me_p = mod_emb + (size_t)(s < Q_ ? 0 : 1) * D_ + i0;
    float4 me = ld4(me_p);
    v.x += pe.x + me.x; v.y += pe.y + me.y; v.z += pe.z + me.z; v.w += pe.w + me.w;
    block_ln(v, i0, emb_g, emb_b, sm);
    st4(x + (size_t)row * D_ + i0, v);
}

// ---------------- residual + LN ----------------
__global__ void add_ln_kernel(const float* __restrict__ y, const float* __restrict__ res,
                              float* __restrict__ out,
                              const float* __restrict__ g, const float* __restrict__ bta) {
    __shared__ float sm[4];
    int row = blockIdx.x;
    int i0 = threadIdx.x * 4;
    size_t off = (size_t)row * D_ + i0;
    float4 a = ld4(y + off), r = ld4(res + off);
    float4 v = make_float4(a.x + r.x, a.y + r.y, a.z + r.z, a.w + r.w);
    block_ln(v, i0, g, bta, sm);
    st4(out + off, v);
}

// ---------------- tiled flash attention ----------------
// block = (b,h) x 64-query tile; 256 threads; K/V tiles in smem with f4-slot swizzle.
// tile layout: 64 rows x 16 float4; chunk c4 of row r stored at slot (c4 + (r>>2)) & 15
__device__ __forceinline__ float4* tsl(float4* base, int r, int c4) {
    return base + r * 16 + ((c4 + (r >> 2)) & 15);
}

__global__ __launch_bounds__(256)
void attn_tile_kernel(const float* __restrict__ q, const float* __restrict__ k,
                      const float* __restrict__ v, const int* __restrict__ mask,
                      float* __restrict__ ctx) {
    extern __shared__ float smdyn[];
    float4* Qs = (float4*)smdyn;            // 1024 f4
    float4* KP = Qs + 1024;                  // K tile, later P tile
    float4* Vs = KP + 1024;
    __shared__ int ms[64];

    int bh = blockIdx.x;
    int b = bh >> 3, h = bh & 7;
    int q0 = blockIdx.y * 64;
    int tid = threadIdx.x;
    int tx = tid & 15, ty = tid >> 4;

    const float* qb = q + (size_t)b * S_ * D_ + h * DH_;
    const float* kb = k + (size_t)b * S_ * D_ + h * DH_;
    const float* vb = v + (size_t)b * S_ * D_ + h * DH_;

    // load Q tile (rows q0..q0+63)
    {
        int r = tid >> 2, c4 = (tid & 3) * 4;
        const float* src = qb + (size_t)(q0 + r) * D_ + c4 * 4;
#pragma unroll
        for (int u = 0; u < 4; ++u)
            *tsl(Qs, r, c4 + u) = ld4(src + u * 4);
    }

    float m[4], l[4], o[4][4];
#pragma unroll
    for (int i = 0; i < 4; ++i) {
        m[i] = -INFINITY; l[i] = 0.0f;
#pragma unroll
        for (int c = 0; c < 4; ++c) o[i][c] = 0.0f;
    }

    for (int kt = 0; kt < 8; ++kt) {
        int k0 = kt * 64;
        __syncthreads();   // previous PV reads done before overwriting KP/Vs
        {
            int r = tid >> 2, c4 = (tid & 3) * 4;
            const float* ks = kb + (size_t)(k0 + r) * D_ + c4 * 4;
            const float* vs = vb + (size_t)(k0 + r) * D_ + c4 * 4;
#pragma unroll
            for (int u = 0; u < 4; ++u) {
                *tsl(KP, r, c4 + u) = ld4(ks + u * 4);
                *tsl(Vs, r, c4 + u) = ld4(vs + u * 4);
            }
            if (tid < 64) ms[tid] = mask[b * S_ + k0 + tid];
        }
        __syncthreads();

        // scores: s[i][j] = sum_d Q[ty*4+i][d] * K[tx*4+j][d]
        float s[4][4];
#pragma unroll
        for (int i = 0; i < 4; ++i)
#pragma unroll
            for (int j = 0; j < 4; ++j) s[i][j] = 0.0f;

        for (int d4 = 0; d4 < 16; ++d4) {
            float4 qv[4], kv[4];
#pragma unroll
            for (int i = 0; i < 4; ++i) qv[i] = *tsl(Qs, ty * 4 + i, d4);
#pragma unroll
            for (int j = 0; j < 4; ++j) kv[j] = *tsl(KP, tx * 4 + j, d4);
#pragma unroll
            for (int i = 0; i < 4; ++i)
#pragma unroll
                for (int j = 0; j < 4; ++j) {
                    s[i][j] = fmaf(qv[i].x, kv[j].x, s[i][j]);
                    s[i][j] = fmaf(qv[i].y, kv[j].y, s[i][j]);
                    s[i][j] = fmaf(qv[i].z, kv[j].z, s[i][j]);
                    s[i][j] = fmaf(qv[i].w, kv[j].w, s[i][j]);
                }
        }
        // mask
#pragma unroll
        for (int j = 0; j < 4; ++j) {
            if (ms[tx * 4 + j] == 0) {
#pragma unroll
                for (int i = 0; i < 4; ++i) s[i][j] = -INFINITY;
            }
        }

        // online softmax update
        float p[4][4], corr[4], psum[4];
#pragma unroll
        for (int i = 0; i < 4; ++i) {
            float rm = fmaxf(fmaxf(s[i][0], s[i][1]), fmaxf(s[i][2], s[i][3]));
#pragma unroll
            for (int off = 1; off < 16; off <<= 1)
                rm = fmaxf(rm, __shfl_xor_sync(0xffffffffu, rm, off));
            float nm = fmaxf(m[i], rm);
            if (nm == -INFINITY) {
                corr[i] = 1.0f;
#pragma unroll
                for (int j = 0; j < 4; ++j) p[i][j] = 0.0f;
            } else {
                corr[i] = __expf(m[i] - nm);
#pragma unroll
                for (int j = 0; j < 4; ++j) p[i][j] = __expf(s[i][j] - nm);
                m[i] = nm;
            }
            float ps = (p[i][0] + p[i][1]) + (p[i][2] + p[i][3]);
#pragma unroll
            for (int off = 1; off < 16; off <<= 1)
                ps += __shfl_xor_sync(0xffffffffu, ps, off);
            psum[i] = ps;
        }

        __syncthreads();   // all score-phase KP reads complete
        // write P into KP: P[row=ty*4+i][col=tx*4+j]
#pragma unroll
        for (int i = 0; i < 4; ++i) {
            int r = ty * 4 + i;
            float* dst = (float*)(KP + r * 16 + ((tx + (r >> 2)) & 15));
#pragma unroll
            for (int j = 0; j < 4; ++j) dst[j] = p[i][j];
        }
#pragma unroll
        for (int i = 0; i < 4; ++i) {
            l[i] = l[i] * corr[i] + psum[i];
#pragma unroll
            for (int c = 0; c < 4; ++c) o[i][c] *= corr[i];
        }
        __syncthreads();

        // PV: o[i][c] += sum_k P[ty*4+i][k] * V[k][tx*4+c]
        for (int kk4 = 0; kk4 < 16; ++kk4) {
            float4 pv[4], vv[4];
#pragma unroll
            for (int i = 0; i < 4; ++i) pv[i] = *tsl(KP, ty * 4 + i, kk4);
#pragma unroll
            for (int u = 0; u < 4; ++u) vv[u] = *tsl(Vs, kk4 * 4 + u, tx);
#pragma unroll
            for (int i = 0; i < 4; ++i) {
                o[i][0] = fmaf(pv[i].x, vv[0].x, o[i][0]);
                o[i][1] = fmaf(pv[i].x, vv[0].y, o[i][1]);
                o[i][2] = fmaf(pv[i].x, vv[0].z, o[i][2]);
                o[i][3] = fmaf(pv[i].x, vv[0].w, o[i][3]);
                o[i][0] = fmaf(pv[i].y, vv[1].x, o[i][0]);
                o[i][1] = fmaf(pv[i].y, vv[1].y, o[i][1]);
                o[i][2] = fmaf(pv[i].y, vv[1].z, o[i][2]);
                o[i][3] = fmaf(pv[i].y, vv[1].w, o[i][3]);
                o[i][0] = fmaf(pv[i].z, vv[2].x, o[i][0]);
                o[i][1] = fmaf(pv[i].z, vv[2].y, o[i][1]);
                o[i][2] = fmaf(pv[i].z, vv[2].z, o[i][2]);
                o[i][3] = fmaf(pv[i].z, vv[2].w, o[i][3]);
                o[i][0] = fmaf(pv[i].w, vv[3].x, o[i][0]);
                o[i][1] = fmaf(pv[i].w, vv[3].y, o[i][1]);
                o[i][2] = fmaf(pv[i].w, vv[3].z, o[i][2]);
                o[i][3] = fmaf(pv[i].w, vv[3].w, o[i][3]);
            }
        }
    }

    // write out: ctx[b, q0+ty*4+i, h*64 + tx*4 + c]
#pragma unroll
    for (int i = 0; i < 4; ++i) {
        float inv = (l[i] > 0.0f) ? (1.0f / l[i]) : 0.0f;
        float4 r = make_float4(o[i][0] * inv, o[i][1] * inv, o[i][2] * inv, o[i][3] * inv);
        st4(ctx + (size_t)(b * S_ + q0 + ty * 4 + i) * D_ + h * DH_ + tx * 4, r);
    }
}

#define ATT_SMEM (3 * 64 * 16 * 16)   // 49152 bytes

// ---------------- launcher ----------------
extern "C" void kernel_launch(void* const* d_in, const int* in_sizes, int n_in,
                              void* d_out, int out_size) {
    const float* video    = (const float*)d_in[0];
    const float* question = (const float*)d_in[1];
    const int*   mask     = (const int*)d_in[2];
    const float* pos_emb  = (const float*)d_in[3];
    const float* mod_emb  = (const float*)d_in[4];
    const float* Wv   = (const float*)d_in[5];
    const float* bv   = (const float*)d_in[6];
    const float* nv_g = (const float*)d_in[7];
    const float* nv_b = (const float*)d_in[8];
    const float* emb_g = (const float*)d_in[9];
    const float* emb_b = (const float*)d_in[10];
    const float* Wq  = (const float*)d_in[11];
    const float* bq  = (const float*)d_in[12];
    const float* Wk  = (const float*)d_in[13];
    const float* bk  = (const float*)d_in[14];
    const float* Wva = (const float*)d_in[15];
    const float* bva = (const float*)d_in[16];
    const float* Wo  = (const float*)d_in[17];
    const float* bo  = (const float*)d_in[18];
    const float* ln1_g = (const float*)d_in[19];
    const float* ln1_b = (const float*)d_in[20];
    const float* W1  = (const float*)d_in[21];
    const float* b1  = (const float*)d_in[22];
    const float* W2  = (const float*)d_in[23];
    const float* b2  = (const float*)d_in[24];
    const float* ln2_g = (const float*)d_in[25];
    const float* ln2_b = (const float*)d_in[26];
    float* out = (float*)d_out;

    float *x, *qb, *kb, *vb, *ctx, *yb, *hb, *vproj;
    __nv_bfloat16 *wh, *wl;
    cudaGetSymbolAddress((void**)&x,     g_x);
    cudaGetSymbolAddress((void**)&qb,    g_q);
    cudaGetSymbolAddress((void**)&kb,    g_k);
    cudaGetSymbolAddress((void**)&vb,    g_v);
    cudaGetSymbolAddress((void**)&ctx,   g_ctx);
    cudaGetSymbolAddress((void**)&yb,    g_y);
    cudaGetSymbolAddress((void**)&hb,    g_h);
    cudaGetSymbolAddress((void**)&vproj, g_vproj);
    cudaGetSymbolAddress((void**)&wh,    g_wh);
    cudaGetSymbolAddress((void**)&wl,    g_wl);

    static bool attr_set = false;
    if (!attr_set) {
        cudaFuncSetAttribute(attn_tile_kernel, cudaFuncAttributeMaxDynamicSharedMemorySize, ATT_SMEM);
        attr_set = true;
    }

    const size_t o_wv = 0;
    const size_t LSTRIDE = 4 * (size_t)D_ * D_ + 2 * (size_t)D_ * FF_;
    const size_t o_l0 = o_wv + (size_t)D_ * FD_;
    auto o_wq = [&](int i) { return o_l0 + i * LSTRIDE + 0 * (size_t)D_ * D_; };
    auto o_wk = [&](int i) { return o_l0 + i * LSTRIDE + 1 * (size_t)D_ * D_; };
    auto o_wa = [&](int i) { return o_l0 + i * LSTRIDE + 2 * (size_t)D_ * D_; };
    auto o_wo = [&](int i) { return o_l0 + i * LSTRIDE + 3 * (size_t)D_ * D_; };
    auto o_w1 = [&](int i) { return o_l0 + i * LSTRIDE + 4 * (size_t)D_ * D_; };
    auto o_w2 = [&](int i) { return o_l0 + i * LSTRIDE + 4 * (size_t)D_ * D_ + (size_t)FF_ * D_; };

    split_w_kernel<<<dim3(D_ / 32, FD_ / 32), dim3(32, 8)>>>(Wv, FD_, D_, wh + o_wv, wl + o_wv);
    for (int i = 0; i < 2; ++i) {
        split_w_kernel<<<dim3(D_ / 32, D_ / 32), dim3(32, 8)>>>(Wq + (size_t)i * D_ * D_, D_, D_, wh + o_wq(i), wl + o_wq(i));
        split_w_kernel<<<dim3(D_ / 32, D_ / 32), dim3(32, 8)>>>(Wk + (size_t)i * D_ * D_, D_, D_, wh + o_wk(i), wl + o_wk(i));
        split_w_kernel<<<dim3(D_ / 32, D_ / 32), dim3(32, 8)>>>(Wva + (size_t)i * D_ * D_, D_, D_, wh + o_wa(i), wl + o_wa(i));
        split_w_kernel<<<dim3(D_ / 32, D_ / 32), dim3(32, 8)>>>(Wo + (size_t)i * D_ * D_, D_, D_, wh + o_wo(i), wl + o_wo(i));
        split_w_kernel<<<dim3(FF_ / 32, D_ / 32), dim3(32, 8)>>>(W1 + (size_t)i * D_ * FF_, D_, FF_, wh + o_w1(i), wl + o_w1(i));
        split_w_kernel<<<dim3(D_ / 32, FF_ / 32), dim3(32, 8)>>>(W2 + (size_t)i * FF_ * D_, FF_, D_, wh + o_w2(i), wl + o_w2(i));
    }

    gemm_tc_kernel<0><<<dim3(D_ / TBN, BT_ / TBM), 256>>>(video, wh + o_wv, wl + o_wv, bv, vproj, BT_, D_, FD_, 1.0f);
    build_x_kernel<<<BS_, 128>>>(question, vproj, pos_emb, mod_emb, nv_g, nv_b, emb_g, emb_b, x);

    const float scale = 0.125f;
    for (int i = 0; i < 2; ++i) {
        gemm_tc_kernel<1><<<dim3(D_ / TBN, BS_ / TBM), 256>>>(x, wh + o_wq(i), wl + o_wq(i), bq + i * D_, qb, BS_, D_, D_, scale);
        gemm_tc_kernel<0><<<dim3(D_ / TBN, BS_ / TBM), 256>>>(x, wh + o_wk(i), wl + o_wk(i), bk + i * D_, kb, BS_, D_, D_, 1.0f);
        gemm_tc_kernel<0><<<dim3(D_ / TBN, BS_ / TBM), 256>>>(x, wh + o_wa(i), wl + o_wa(i), bva + i * D_, vb, BS_, D_, D_, 1.0f);

        attn_tile_kernel<<<dim3(B_ * H_, S_ / 64), 256, ATT_SMEM>>>(qb, kb, vb, mask, ctx);

        gemm_tc_kernel<0><<<dim3(D_ / TBN, BS_ / TBM), 256>>>(ctx, wh + o_wo(i), wl + o_wo(i), bo + i * D_, yb, BS_, D_, D_, 1.0f);
        add_ln_kernel<<<BS_, 128>>>(yb, x, x, ln1_g + i * D_, ln1_b + i * D_);

        gemm_tc_kernel<2><<<dim3(FF_ / TBN, BS_ / TBM), 256>>>(x, wh + o_w1(i), wl + o_w1(i), b1 + i * FF_, hb, BS_, FF_, D_, 1.0f);
        gemm_tc_kernel<0><<<dim3(D_ / TBN, BS_ / TBM), 256>>>(hb, wh + o_w2(i), wl + o_w2(i), b2 + i * D_, yb, BS_, D_, FF_, 1.0f);

        float* dst = (i == 1) ? out : x;
        add_ln_kernel<<<BS_, 128>>>(yb, x, dst, ln2_g + i * D_, ln2_b + i * D_);
    }
    (void)in_sizes; (void)n_in; (void)out_size;
}

// round 6
// speedup vs baseline: 3.5313x; 1.1233x over previous
#include <cuda_runtime.h>
#include <cuda_bf16.h>
#include <math.h>
#include <stdint.h>

#define B_   64
#define Q_   64
#define T_   448
#define D_   512
#define FD_  1024
#define H_   8
#define DH_  64
#define FF_  2048
#define S_   512
#define BS_  (B_ * S_)   // 32768
#define BT_  (B_ * T_)   // 28672

// ---------------- scratch (static device globals; no allocation) ----------------
__device__ float g_x[BS_ * D_];
__device__ float g_q[BS_ * D_];
__device__ float g_k[BS_ * D_];
__device__ float g_v[BS_ * D_];
__device__ float g_y[BS_ * D_];
__device__ float g_vproj[(size_t)BT_ * D_];

// bf16 hi/lo split activations
__device__ __nv_bfloat16 g_xh[BS_ * D_], g_xl[BS_ * D_];
__device__ __nv_bfloat16 g_ch[BS_ * D_], g_cl[BS_ * D_];
__device__ __nv_bfloat16 g_hh[(size_t)BS_ * FF_], g_hl[(size_t)BS_ * FF_];
__device__ __nv_bfloat16 g_vh[(size_t)BT_ * FD_], g_vl[(size_t)BT_ * FD_];

// split/transposed weights: hi + lo bf16, layout [N][K]
#define WSPLIT_TOTAL 6815744
__device__ __nv_bfloat16 g_wh[WSPLIT_TOTAL];
__device__ __nv_bfloat16 g_wl[WSPLIT_TOTAL];

// ---------------- small helpers ----------------
__device__ __forceinline__ float4 ld4(const float* p) { return *(const float4*)p; }
__device__ __forceinline__ void st4(float* p, float4 v) { *(float4*)p = v; }

__device__ __forceinline__ void split_store4(__nv_bfloat16* __restrict__ hp,
                                             __nv_bfloat16* __restrict__ lp,
                                             size_t off, float4 v) {
    __nv_bfloat16 h0 = __float2bfloat16(v.x);
    __nv_bfloat16 h1 = __float2bfloat16(v.y);
    __nv_bfloat16 h2 = __float2bfloat16(v.z);
    __nv_bfloat16 h3 = __float2bfloat16(v.w);
    __nv_bfloat16 l0 = __float2bfloat16(v.x - __bfloat162float(h0));
    __nv_bfloat16 l1 = __float2bfloat16(v.y - __bfloat162float(h1));
    __nv_bfloat16 l2 = __float2bfloat16(v.z - __bfloat162float(h2));
    __nv_bfloat16 l3 = __float2bfloat16(v.w - __bfloat162float(h3));
    *(__nv_bfloat162*)(hp + off)     = __nv_bfloat162(h0, h1);
    *(__nv_bfloat162*)(hp + off + 2) = __nv_bfloat162(h2, h3);
    *(__nv_bfloat162*)(lp + off)     = __nv_bfloat162(l0, l1);
    *(__nv_bfloat162*)(lp + off + 2) = __nv_bfloat162(l2, l3);
}

__device__ __forceinline__ float block_sum(float v, float* sm) {
#pragma unroll
    for (int o = 16; o; o >>= 1) v += __shfl_xor_sync(0xffffffffu, v, o);
    int w = threadIdx.x >> 5;
    __syncthreads();
    if ((threadIdx.x & 31) == 0) sm[w] = v;
    __syncthreads();
    return (sm[0] + sm[1]) + (sm[2] + sm[3]);
}

__device__ __forceinline__ void block_ln(float4& v, int i0,
                                         const float* __restrict__ g,
                                         const float* __restrict__ b,
                                         float* sm) {
    float s = v.x + v.y + v.z + v.w;
    s = block_sum(s, sm);
    float mean = s * (1.0f / (float)D_);
    float dx = v.x - mean, dy = v.y - mean, dz = v.z - mean, dw = v.w - mean;
    float ss = dx * dx + dy * dy + dz * dz + dw * dw;
    ss = block_sum(ss, sm);
    float inv = rsqrtf(ss * (1.0f / (float)D_) + 1e-12f);
    float4 gg = ld4(g + i0), bb = ld4(b + i0);
    v.x = dx * inv * gg.x + bb.x;
    v.y = dy * inv * gg.y + bb.y;
    v.z = dz * inv * gg.z + bb.z;
    v.w = dw * inv * gg.w + bb.w;
}

// ---------------- weight transpose+split: T[n][k] = W[k][n] as bf16 hi/lo ----------------
__global__ void split_w_kernel(const float* __restrict__ W, int K, int N,
                               __nv_bfloat16* __restrict__ Th, __nv_bfloat16* __restrict__ Tl) {
    __shared__ float tile[32][33];
    int k0 = blockIdx.y * 32, n0 = blockIdx.x * 32;
    int tx = threadIdx.x, ty = threadIdx.y;
    for (int j = ty; j < 32; j += 8)
        tile[j][tx] = W[(size_t)(k0 + j) * N + n0 + tx];
    __syncthreads();
    for (int j = ty; j < 32; j += 8) {
        float v = tile[tx][j];
        __nv_bfloat16 hi = __float2bfloat16(v);
        __nv_bfloat16 lo = __float2bfloat16(v - __bfloat162float(hi));
        size_t o = (size_t)(n0 + j) * K + k0 + tx;
        Th[o] = hi; Tl[o] = lo;
    }
}

// ---------------- plain elementwise split (video) ----------------
__global__ void split_a_kernel(const float* __restrict__ A,
                               __nv_bfloat16* __restrict__ Ah, __nv_bfloat16* __restrict__ Al) {
    size_t i = ((size_t)blockIdx.x * 256 + threadIdx.x) * 4;
    float4 v = ld4(A + i);
    split_store4(Ah, Al, i, v);
}

// ---------------- mma.sync GEMM, presplit bf16 inputs, cp.async double buffer ----------------
// C = epilogue(A @ W^T + bias); A presplit [M][K] hi/lo, W presplit [N][K] hi/lo
// MODE: 0 bias->f32, 1 bias*scale->f32, 2 gelu(bias)->bf16 hi/lo split
#define GLDA 40   // 32 + 8 pad bf16 elems -> 80B row stride
#define ARR  (128 * GLDA)            // elems per array
#define BUFE (4 * ARR)               // elems per buffer (Ah, Al, Bh, Bl)
#define GT2_SMEM (2 * BUFE * 2)      // bytes: 2 buffers -> 81920

__device__ __forceinline__ void mma16816(float* d, const unsigned* a, const unsigned* b) {
    asm volatile(
        "mma.sync.aligned.m16n8k16.row.col.f32.bf16.bf16.f32 "
        "{%0,%1,%2,%3}, {%4,%5,%6,%7}, {%8,%9}, {%0,%1,%2,%3};\n"
        : "+f"(d[0]), "+f"(d[1]), "+f"(d[2]), "+f"(d[3])
        : "r"(a[0]), "r"(a[1]), "r"(a[2]), "r"(a[3]), "r"(b[0]), "r"(b[1]));
}
__device__ __forceinline__ void ldsm4(unsigned* r, unsigned addr) {
    asm volatile("ldmatrix.sync.aligned.m8n8.x4.shared.b16 {%0,%1,%2,%3}, [%4];\n"
                 : "=r"(r[0]), "=r"(r[1]), "=r"(r[2]), "=r"(r[3]) : "r"(addr));
}
__device__ __forceinline__ void ldsm2(unsigned* r, unsigned addr) {
    asm volatile("ldmatrix.sync.aligned.m8n8.x2.shared.b16 {%0,%1}, [%2];\n"
                 : "=r"(r[0]), "=r"(r[1]) : "r"(addr));
}
__device__ __forceinline__ void cpasync16(uint32_t dst, const void* src) {
    asm volatile("cp.async.cg.shared.global [%0], [%1], 16;" :: "r"(dst), "l"(src));
}
#define CP_COMMIT() asm volatile("cp.async.commit_group;" ::: "memory")
#define CP_WAIT1()  asm volatile("cp.async.wait_group 1;" ::: "memory")
#define CP_WAIT0()  asm volatile("cp.async.wait_group 0;" ::: "memory")

template<int MODE>
__global__ __launch_bounds__(256, 2)
void gemm_bf16(const __nv_bfloat16* __restrict__ Ah_g, const __nv_bfloat16* __restrict__ Al_g,
               const __nv_bfloat16* __restrict__ Wh_g, const __nv_bfloat16* __restrict__ Wl_g,
               const float* __restrict__ bias,
               float* __restrict__ C,
               __nv_bfloat16* __restrict__ Ch, __nv_bfloat16* __restrict__ Cl,
               int M, int N, int K, float scale) {
    extern __shared__ __nv_bfloat16 smg[];

    int tid = threadIdx.x;
    int lane = tid & 31, wid = tid >> 5;
    int warpM = wid & 1, warpN = wid >> 1;   // 2 x 4 warps
    int m0 = warpM * 64, n0 = warpN * 32;

    int blockM = blockIdx.y * 128;
    int blockN = blockIdx.x * 128;

    int a_row = lane & 15, a_cs = (lane >> 4) * 8;
    int b_row = lane & 7,  b_cs = ((lane >> 3) & 1) * 8;

    float acc[4][4][4];
#pragma unroll
    for (int f = 0; f < 4; ++f)
#pragma unroll
        for (int g = 0; g < 4; ++g)
#pragma unroll
            for (int j = 0; j < 4; ++j) acc[f][g][j] = 0.0f;

    // staging: 512 (r,c8) pairs per array, 2 per thread
    int sr[2], sc[2];
#pragma unroll
    for (int wv = 0; wv < 2; ++wv) {
        int idx = tid + wv * 256;
        sr[wv] = idx >> 2;
        sc[wv] = (idx & 3) * 8;
    }

    auto stage = [&](int kt, int buf) {
        __nv_bfloat16* base = smg + buf * BUFE;
#pragma unroll
        for (int wv = 0; wv < 2; ++wv) {
            int r = sr[wv], c8 = sc[wv];
            uint32_t dsm = (uint32_t)__cvta_generic_to_shared(base + r * GLDA + c8);
            size_t ga = (size_t)(blockM + r) * K + kt * 32 + c8;
            size_t gb = (size_t)(blockN + r) * K + kt * 32 + c8;
            cpasync16(dsm,               Ah_g + ga);
            cpasync16(dsm + ARR * 2,     Al_g + ga);
            cpasync16(dsm + 2 * ARR * 2, Wh_g + gb);
            cpasync16(dsm + 3 * ARR * 2, Wl_g + gb);
        }
    };

    int T = K >> 5;
    stage(0, 0);
    CP_COMMIT();

    for (int kt = 0; kt < T; ++kt) {
        int buf = kt & 1;
        if (kt + 1 < T) { stage(kt + 1, buf ^ 1); CP_COMMIT(); CP_WAIT1(); }
        else            { CP_WAIT0(); }
        __syncthreads();

        __nv_bfloat16* Ahs = smg + buf * BUFE;
        __nv_bfloat16* Als = Ahs + ARR;
        __nv_bfloat16* Bhs = Ahs + 2 * ARR;
        __nv_bfloat16* Bls = Ahs + 3 * ARR;

#pragma unroll
        for (int kc = 0; kc < 32; kc += 16) {
            unsigned aF[16], bHf[8], bLf[8];
#pragma unroll
            for (int f = 0; f < 4; ++f)
                ldsm4(aF + 4 * f, (unsigned)__cvta_generic_to_shared(
                    Ahs + (m0 + f * 16 + a_row) * GLDA + kc + a_cs));
#pragma unroll
            for (int g = 0; g < 4; ++g)
                ldsm2(bHf + 2 * g, (unsigned)__cvta_generic_to_shared(
                    Bhs + (n0 + g * 8 + b_row) * GLDA + kc + b_cs));
#pragma unroll
            for (int g = 0; g < 4; ++g)
                ldsm2(bLf + 2 * g, (unsigned)__cvta_generic_to_shared(
                    Bls + (n0 + g * 8 + b_row) * GLDA + kc + b_cs));
            // hi*hi
#pragma unroll
            for (int f = 0; f < 4; ++f)
#pragma unroll
                for (int g = 0; g < 4; ++g)
                    mma16816(acc[f][g], aF + 4 * f, bHf + 2 * g);
            // hi*lo
#pragma unroll
            for (int f = 0; f < 4; ++f)
#pragma unroll
                for (int g = 0; g < 4; ++g)
                    mma16816(acc[f][g], aF + 4 * f, bLf + 2 * g);
            // lo*hi
#pragma unroll
            for (int f = 0; f < 4; ++f)
                ldsm4(aF + 4 * f, (unsigned)__cvta_generic_to_shared(
                    Als + (m0 + f * 16 + a_row) * GLDA + kc + a_cs));
#pragma unroll
            for (int f = 0; f < 4; ++f)
#pragma unroll
                for (int g = 0; g < 4; ++g)
                    mma16816(acc[f][g], aF + 4 * f, bHf + 2 * g);
        }
        __syncthreads();
    }

    // ---- epilogue ----
#pragma unroll
    for (int f = 0; f < 4; ++f) {
#pragma unroll
        for (int g = 0; g < 4; ++g) {
            int col = blockN + n0 + g * 8 + (lane & 3) * 2;
            float b0 = bias[col], b1 = bias[col + 1];
#pragma unroll
            for (int half = 0; half < 2; ++half) {
                int row = blockM + m0 + f * 16 + (lane >> 2) + half * 8;
                float v0 = acc[f][g][half * 2 + 0] + b0;
                float v1 = acc[f][g][half * 2 + 1] + b1;
                if (MODE == 1) { v0 *= scale; v1 *= scale; }
                if (MODE == 2) {
                    v0 = 0.5f * v0 * (1.0f + erff(v0 * 0.70710678118654752f));
                    v1 = 0.5f * v1 * (1.0f + erff(v1 * 0.70710678118654752f));
                    __nv_bfloat16 h0 = __float2bfloat16(v0);
                    __nv_bfloat16 h1 = __float2bfloat16(v1);
                    __nv_bfloat16 l0 = __float2bfloat16(v0 - __bfloat162float(h0));
                    __nv_bfloat16 l1 = __float2bfloat16(v1 - __bfloat162float(h1));
                    size_t off = (size_t)row * N + col;
                    *(__nv_bfloat162*)(Ch + off) = __nv_bfloat162(h0, h1);
                    *(__nv_bfloat162*)(Cl + off) = __nv_bfloat162(l0, l1);
                } else {
                    *(float2*)&C[(size_t)row * N + col] = make_float2(v0, v1);
                }
            }
        }
    }
}

// ---------------- build x: concat(question, LN(vproj)) + pos + mod, LN; emit f32 + hi/lo ----------------
__global__ void build_x_kernel(const float* __restrict__ question,
                               const float* __restrict__ vproj,
                               const float* __restrict__ pos_emb,
                               const float* __restrict__ mod_emb,
                               const float* __restrict__ nv_g, const float* __restrict__ nv_b,
                               const float* __restrict__ emb_g, const float* __restrict__ emb_b,
                               float* __restrict__ x,
                               __nv_bfloat16* __restrict__ xh, __nv_bfloat16* __restrict__ xl) {
    __shared__ float sm[4];
    int row = blockIdx.x;
    int b = row / S_, s = row % S_;
    int i0 = threadIdx.x * 4;
    float4 v;
    if (s < Q_) {
        v = ld4(question + ((size_t)b * Q_ + s) * D_ + i0);
    } else {
        v = ld4(vproj + ((size_t)b * T_ + (s - Q_)) * D_ + i0);
        block_ln(v, i0, nv_g, nv_b, sm);
    }
    float4 pe = ld4(pos_emb + (size_t)s * D_ + i0);
    const float* me_p = mod_emb + (size_t)(s < Q_ ? 0 : 1) * D_ + i0;
    float4 me = ld4(me_p);
    v.x += pe.x + me.x; v.y += pe.y + me.y; v.z += pe.z + me.z; v.w += pe.w + me.w;
    block_ln(v, i0, emb_g, emb_b, sm);
    size_t off = (size_t)row * D_ + i0;
    st4(x + off, v);
    split_store4(xh, xl, off, v);
}

// ---------------- residual + LN; emit f32 + hi/lo ----------------
__global__ void add_ln_kernel(const float* __restrict__ y, const float* __restrict__ res,
                              float* __restrict__ out,
                              __nv_bfloat16* __restrict__ oh, __nv_bfloat16* __restrict__ ol,
                              const float* __restrict__ g, const float* __restrict__ bta) {
    __shared__ float sm[4];
    int row = blockIdx.x;
    int i0 = threadIdx.x * 4;
    size_t off = (size_t)row * D_ + i0;
    float4 a = ld4(y + off), r = ld4(res + off);
    float4 v = make_float4(a.x + r.x, a.y + r.y, a.z + r.z, a.w + r.w);
    block_ln(v, i0, g, bta, sm);
    st4(out + off, v);
    split_store4(oh, ol, off, v);
}

// ---------------- tiled flash attention (f32 in, bf16 hi/lo ctx out) ----------------
__device__ __forceinline__ float4* tsl(float4* base, int r, int c4) {
    return base + r * 16 + ((c4 + (r >> 2)) & 15);
}

__global__ __launch_bounds__(256)
void attn_tile_kernel(const float* __restrict__ q, const float* __restrict__ k,
                      const float* __restrict__ v, const int* __restrict__ mask,
                      __nv_bfloat16* __restrict__ ch, __nv_bfloat16* __restrict__ cl) {
    extern __shared__ float smdyn[];
    float4* Qs = (float4*)smdyn;
    float4* KP = Qs + 1024;
    float4* Vs = KP + 1024;
    __shared__ int ms[64];

    int bh = blockIdx.x;
    int b = bh >> 3, h = bh & 7;
    int q0 = blockIdx.y * 64;
    int tid = threadIdx.x;
    int tx = tid & 15, ty = tid >> 4;

    const float* qb = q + (size_t)b * S_ * D_ + h * DH_;
    const float* kb = k + (size_t)b * S_ * D_ + h * DH_;
    const float* vb = v + (size_t)b * S_ * D_ + h * DH_;

    {
        int r = tid >> 2, c4 = (tid & 3) * 4;
        const float* src = qb + (size_t)(q0 + r) * D_ + c4 * 4;
#pragma unroll
        for (int u = 0; u < 4; ++u)
            *tsl(Qs, r, c4 + u) = ld4(src + u * 4);
    }

    float m[4], l[4], o[4][4];
#pragma unroll
    for (int i = 0; i < 4; ++i) {
        m[i] = -INFINITY; l[i] = 0.0f;
#pragma unroll
        for (int c = 0; c < 4; ++c) o[i][c] = 0.0f;
    }

    for (int kt = 0; kt < 8; ++kt) {
        int k0 = kt * 64;
        __syncthreads();
        {
            int r = tid >> 2, c4 = (tid & 3) * 4;
            const float* ks = kb + (size_t)(k0 + r) * D_ + c4 * 4;
            const float* vs = vb + (size_t)(k0 + r) * D_ + c4 * 4;
#pragma unroll
            for (int u = 0; u < 4; ++u) {
                *tsl(KP, r, c4 + u) = ld4(ks + u * 4);
                *tsl(Vs, r, c4 + u) = ld4(vs + u * 4);
            }
            if (tid < 64) ms[tid] = mask[b * S_ + k0 + tid];
        }
        __syncthreads();

        float s[4][4];
#pragma unroll
        for (int i = 0; i < 4; ++i)
#pragma unroll
            for (int j = 0; j < 4; ++j) s[i][j] = 0.0f;

        for (int d4 = 0; d4 < 16; ++d4) {
            float4 qv[4], kv[4];
#pragma unroll
            for (int i = 0; i < 4; ++i) qv[i] = *tsl(Qs, ty * 4 + i, d4);
#pragma unroll
            for (int j = 0; j < 4; ++j) kv[j] = *tsl(KP, tx * 4 + j, d4);
#pragma unroll
            for (int i = 0; i < 4; ++i)
#pragma unroll
                for (int j = 0; j < 4; ++j) {
                    s[i][j] = fmaf(qv[i].x, kv[j].x, s[i][j]);
                    s[i][j] = fmaf(qv[i].y, kv[j].y, s[i][j]);
                    s[i][j] = fmaf(qv[i].z, kv[j].z, s[i][j]);
                    s[i][j] = fmaf(qv[i].w, kv[j].w, s[i][j]);
                }
        }
#pragma unroll
        for (int j = 0; j < 4; ++j) {
            if (ms[tx * 4 + j] == 0) {
#pragma unroll
                for (int i = 0; i < 4; ++i) s[i][j] = -INFINITY;
            }
        }

        float p[4][4], corr[4], psum[4];
#pragma unroll
        for (int i = 0; i < 4; ++i) {
            float rm = fmaxf(fmaxf(s[i][0], s[i][1]), fmaxf(s[i][2], s[i][3]));
#pragma unroll
            for (int off = 1; off < 16; off <<= 1)
                rm = fmaxf(rm, __shfl_xor_sync(0xffffffffu, rm, off));
            float nm = fmaxf(m[i], rm);
            if (nm == -INFINITY) {
                corr[i] = 1.0f;
#pragma unroll
                for (int j = 0; j < 4; ++j) p[i][j] = 0.0f;
            } else {
                corr[i] = __expf(m[i] - nm);
#pragma unroll
                for (int j = 0; j < 4; ++j) p[i][j] = __expf(s[i][j] - nm);
                m[i] = nm;
            }
            float ps = (p[i][0] + p[i][1]) + (p[i][2] + p[i][3]);
#pragma unroll
            for (int off = 1; off < 16; off <<= 1)
                ps += __shfl_xor_sync(0xffffffffu, ps, off);
            psum[i] = ps;
        }

        __syncthreads();
#pragma unroll
        for (int i = 0; i < 4; ++i) {
            int r = ty * 4 + i;
            float* dst = (float*)(KP + r * 16 + ((tx + (r >> 2)) & 15));
#pragma unroll
            for (int j = 0; j < 4; ++j) dst[j] = p[i][j];
        }
#pragma unroll
        for (int i = 0; i < 4; ++i) {
            l[i] = l[i] * corr[i] + psum[i];
#pragma unroll
            for (int c = 0; c < 4; ++c) o[i][c] *= corr[i];
        }
        __syncthreads();

        for (int kk4 = 0; kk4 < 16; ++kk4) {
            float4 pv[4], vv[4];
#pragma unroll
            for (int i = 0; i < 4; ++i) pv[i] = *tsl(KP, ty * 4 + i, kk4);
#pragma unroll
            for (int u = 0; u < 4; ++u) vv[u] = *tsl(Vs, kk4 * 4 + u, tx);
#pragma unroll
            for (int i = 0; i < 4; ++i) {
                o[i][0] = fmaf(pv[i].x, vv[0].x, o[i][0]);
                o[i][1] = fmaf(pv[i].x, vv[0].y, o[i][1]);
                o[i][2] = fmaf(pv[i].x, vv[0].z, o[i][2]);
                o[i][3] = fmaf(pv[i].x, vv[0].w, o[i][3]);
                o[i][0] = fmaf(pv[i].y, vv[1].x, o[i][0]);
                o[i][1] = fmaf(pv[i].y, vv[1].y, o[i][1]);
                o[i][2] = fmaf(pv[i].y, vv[1].z, o[i][2]);
                o[i][3] = fmaf(pv[i].y, vv[1].w, o[i][3]);
                o[i][0] = fmaf(pv[i].z, vv[2].x, o[i][0]);
                o[i][1] = fmaf(pv[i].z, vv[2].y, o[i][1]);
                o[i][2] = fmaf(pv[i].z, vv[2].z, o[i][2]);
                o[i][3] = fmaf(pv[i].z, vv[2].w, o[i][3]);
                o[i][0] = fmaf(pv[i].w, vv[3].x, o[i][0]);
                o[i][1] = fmaf(pv[i].w, vv[3].y, o[i][1]);
                o[i][2] = fmaf(pv[i].w, vv[3].z, o[i][2]);
                o[i][3] = fmaf(pv[i].w, vv[3].w, o[i][3]);
            }
        }
    }

#pragma unroll
    for (int i = 0; i < 4; ++i) {
        float inv = (l[i] > 0.0f) ? (1.0f / l[i]) : 0.0f;
        float4 r = make_float4(o[i][0] * inv, o[i][1] * inv, o[i][2] * inv, o[i][3] * inv);
        size_t off = (size_t)(b * S_ + q0 + ty * 4 + i) * D_ + h * DH_ + tx * 4;
        split_store4(ch, cl, off, r);
    }
}

#define ATT_SMEM (3 * 64 * 16 * 16)   // 49152 bytes

// ---------------- launcher ----------------
extern "C" void kernel_launch(void* const* d_in, const int* in_sizes, int n_in,
                              void* d_out, int out_size) {
    const float* video    = (const float*)d_in[0];
    const float* question = (const float*)d_in[1];
    const int*   mask     = (const int*)d_in[2];
    const float* pos_emb  = (const float*)d_in[3];
    const float* mod_emb  = (const float*)d_in[4];
    const float* Wv   = (const float*)d_in[5];
    const float* bv   = (const float*)d_in[6];
    const float* nv_g = (const float*)d_in[7];
    const float* nv_b = (const float*)d_in[8];
    const float* emb_g = (const float*)d_in[9];
    const float* emb_b = (const float*)d_in[10];
    const float* Wq  = (const float*)d_in[11];
    const float* bq  = (const float*)d_in[12];
    const float* Wk  = (const float*)d_in[13];
    const float* bk  = (const float*)d_in[14];
    const float* Wva = (const float*)d_in[15];
    const float* bva = (const float*)d_in[16];
    const float* Wo  = (const float*)d_in[17];
    const float* bo  = (const float*)d_in[18];
    const float* ln1_g = (const float*)d_in[19];
    const float* ln1_b = (const float*)d_in[20];
    const float* W1  = (const float*)d_in[21];
    const float* b1  = (const float*)d_in[22];
    const float* W2  = (const float*)d_in[23];
    const float* b2  = (const float*)d_in[24];
    const float* ln2_g = (const float*)d_in[25];
    const float* ln2_b = (const float*)d_in[26];
    float* out = (float*)d_out;

    float *x, *qb, *kb, *vb, *yb, *vproj;
    __nv_bfloat16 *wh, *wl, *xh, *xl, *ch, *cl, *hh, *hl, *vh, *vl;
    cudaGetSymbolAddress((void**)&x,     g_x);
    cudaGetSymbolAddress((void**)&qb,    g_q);
    cudaGetSymbolAddress((void**)&kb,    g_k);
    cudaGetSymbolAddress((void**)&vb,    g_v);
    cudaGetSymbolAddress((void**)&yb,    g_y);
    cudaGetSymbolAddress((void**)&vproj, g_vproj);
    cudaGetSymbolAddress((void**)&wh,    g_wh);
    cudaGetSymbolAddress((void**)&wl,    g_wl);
    cudaGetSymbolAddress((void**)&xh,    g_xh);
    cudaGetSymbolAddress((void**)&xl,    g_xl);
    cudaGetSymbolAddress((void**)&ch,    g_ch);
    cudaGetSymbolAddress((void**)&cl,    g_cl);
    cudaGetSymbolAddress((void**)&hh,    g_hh);
    cudaGetSymbolAddress((void**)&hl,    g_hl);
    cudaGetSymbolAddress((void**)&vh,    g_vh);
    cudaGetSymbolAddress((void**)&vl,    g_vl);

    static bool attr_set = false;
    if (!attr_set) {
        cudaFuncSetAttribute(attn_tile_kernel, cudaFuncAttributeMaxDynamicSharedMemorySize, ATT_SMEM);
        cudaFuncSetAttribute(gemm_bf16<0>, cudaFuncAttributeMaxDynamicSharedMemorySize, GT2_SMEM);
        cudaFuncSetAttribute(gemm_bf16<1>, cudaFuncAttributeMaxDynamicSharedMemorySize, GT2_SMEM);
        cudaFuncSetAttribute(gemm_bf16<2>, cudaFuncAttributeMaxDynamicSharedMemorySize, GT2_SMEM);
        attr_set = true;
    }

    const size_t o_wv = 0;
    const size_t LSTRIDE = 4 * (size_t)D_ * D_ + 2 * (size_t)D_ * FF_;
    const size_t o_l0 = o_wv + (size_t)D_ * FD_;
    auto o_wq = [&](int i) { return o_l0 + i * LSTRIDE + 0 * (size_t)D_ * D_; };
    auto o_wk = [&](int i) { return o_l0 + i * LSTRIDE + 1 * (size_t)D_ * D_; };
    auto o_wa = [&](int i) { return o_l0 + i * LSTRIDE + 2 * (size_t)D_ * D_; };
    auto o_wo = [&](int i) { return o_l0 + i * LSTRIDE + 3 * (size_t)D_ * D_; };
    auto o_w1 = [&](int i) { return o_l0 + i * LSTRIDE + 4 * (size_t)D_ * D_; };
    auto o_w2 = [&](int i) { return o_l0 + i * LSTRIDE + 4 * (size_t)D_ * D_ + (size_t)FF_ * D_; };

    split_w_kernel<<<dim3(D_ / 32, FD_ / 32), dim3(32, 8)>>>(Wv, FD_, D_, wh + o_wv, wl + o_wv);
    for (int i = 0; i < 2; ++i) {
        split_w_kernel<<<dim3(D_ / 32, D_ / 32), dim3(32, 8)>>>(Wq + (size_t)i * D_ * D_, D_, D_, wh + o_wq(i), wl + o_wq(i));
        split_w_kernel<<<dim3(D_ / 32, D_ / 32), dim3(32, 8)>>>(Wk + (size_t)i * D_ * D_, D_, D_, wh + o_wk(i), wl + o_wk(i));
        split_w_kernel<<<dim3(D_ / 32, D_ / 32), dim3(32, 8)>>>(Wva + (size_t)i * D_ * D_, D_, D_, wh + o_wa(i), wl + o_wa(i));
        split_w_kernel<<<dim3(D_ / 32, D_ / 32), dim3(32, 8)>>>(Wo + (size_t)i * D_ * D_, D_, D_, wh + o_wo(i), wl + o_wo(i));
        split_w_kernel<<<dim3(FF_ / 32, D_ / 32), dim3(32, 8)>>>(W1 + (size_t)i * D_ * FF_, D_, FF_, wh + o_w1(i), wl + o_w1(i));
        split_w_kernel<<<dim3(D_ / 32, FF_ / 32), dim3(32, 8)>>>(W2 + (size_t)i * FF_ * D_, FF_, D_, wh + o_w2(i), wl + o_w2(i));
    }

    // video split + projection
    split_a_kernel<<<(BT_ * FD_) / 1024, 256>>>(video, vh, vl);
    gemm_bf16<0><<<dim3(D_ / 128, BT_ / 128), 256, GT2_SMEM>>>(vh, vl, wh + o_wv, wl + o_wv, bv,
                                                               vproj, nullptr, nullptr, BT_, D_, FD_, 1.0f);
    build_x_kernel<<<BS_, 128>>>(question, vproj, pos_emb, mod_emb, nv_g, nv_b, emb_g, emb_b, x, xh, xl);

    const float scale = 0.125f;
    for (int i = 0; i < 2; ++i) {
        gemm_bf16<1><<<dim3(D_ / 128, BS_ / 128), 256, GT2_SMEM>>>(xh, xl, wh + o_wq(i), wl + o_wq(i), bq + i * D_,
                                                                   qb, nullptr, nullptr, BS_, D_, D_, scale);
        gemm_bf16<0><<<dim3(D_ / 128, BS_ / 128), 256, GT2_SMEM>>>(xh, xl, wh + o_wk(i), wl + o_wk(i), bk + i * D_,
                                                                   kb, nullptr, nullptr, BS_, D_, D_, 1.0f);
        gemm_bf16<0><<<dim3(D_ / 128, BS_ / 128), 256, GT2_SMEM>>>(xh, xl, wh + o_wa(i), wl + o_wa(i), bva + i * D_,
                                                                   vb, nullptr, nullptr, BS_, D_, D_, 1.0f);

        attn_tile_kernel<<<dim3(B_ * H_, S_ / 64), 256, ATT_SMEM>>>(qb, kb, vb, mask, ch, cl);

        gemm_bf16<0><<<dim3(D_ / 128, BS_ / 128), 256, GT2_SMEM>>>(ch, cl, wh + o_wo(i), wl + o_wo(i), bo + i * D_,
                                                                   yb, nullptr, nullptr, BS_, D_, D_, 1.0f);
        add_ln_kernel<<<BS_, 128>>>(yb, x, x, xh, xl, ln1_g + i * D_, ln1_b + i * D_);

        gemm_bf16<2><<<dim3(FF_ / 128, BS_ / 128), 256, GT2_SMEM>>>(xh, xl, wh + o_w1(i), wl + o_w1(i), b1 + i * FF_,
                                                                    nullptr, hh, hl, BS_, FF_, D_, 1.0f);
        gemm_bf16<0><<<dim3(D_ / 128, BS_ / 128), 256, GT2_SMEM>>>(hh, hl, wh + o_w2(i), wl + o_w2(i), b2 + i * D_,
                                                                   yb, nullptr, nullptr, BS_, D_, FF_, 1.0f);

        float* dst = (i == 1) ? out : x;
        add_ln_kernel<<<BS_, 128>>>(yb, x, dst, xh, xl, ln2_g + i * D_, ln2_b + i * D_);
    }
    (void)in_sizes; (void)n_in; (void)out_size;
}